// round 8
// baseline (speedup 1.0000x reference)
#include <cuda_runtime.h>
#include <math.h>

// Problem constants
#define BB   32
#define LL   2048
#define DIN  64
#define NC   32
#define DC   16
#define OUTD 512           // NC*DC
#define EPSQ 1e-7f

#define K1_CHUNKS 16
#define K3_CHUNKS 8        // blocks per batch in routing pass (256 l's each)
#define K3_WARPS  4
#define K3_LPW    64       // l's per warp

// Scratch (static device allocations only — no cudaMalloc allowed)
__device__ float g_colsum_part[BB][K1_CHUNKS][DIN];
__device__ float g_s_part[2][BB][K3_CHUNKS][NC][DIN];   // ping-pong, 2 MB each
__device__ float g_v_unused;   // (kept out: v now lives in smem per block)

// ---------------------------------------------------------------------------
// K1: column sums  colsum_part[b][chunk][i] = sum over 128 l's of u[b,l,i]
// grid (K1_CHUNKS, BB), 256 threads
// ---------------------------------------------------------------------------
__global__ void k1_colsum(const float* __restrict__ u) {
    const int b = blockIdx.y, chunk = blockIdx.x;
    const int tid = threadIdx.x;
    const int col4 = tid & 15;
    const int g    = tid >> 4;

    const float4* up = (const float4*)(u + ((size_t)b * LL + (size_t)chunk * 128) * DIN);
    float4 acc = make_float4(0.f, 0.f, 0.f, 0.f);
    #pragma unroll
    for (int r = 0; r < 8; r++) {
        float4 x = up[(size_t)(g + r * 16) * 16 + col4];
        acc.x += x.x; acc.y += x.y; acc.z += x.z; acc.w += x.w;
    }
    __shared__ float4 red[16][16];
    red[g][col4] = acc;
    __syncthreads();
    if (tid < 16) {
        float4 s = red[0][tid];
        #pragma unroll
        for (int i = 1; i < 16; i++) {
            float4 x = red[i][tid];
            s.x += x.x; s.y += x.y; s.z += x.z; s.w += x.w;
        }
        ((float4*)g_colsum_part[b][chunk])[tid] = s;
    }
}

// ---------------------------------------------------------------------------
// K3: fused prologue + routing pass.
// Prologue (redundant per block, ~2us chip-wide): build s for this batch
// (iter 1: from colsum, uniform c=1/32; iter 2: from g_s_part[0]),
// raw = s.W, out = squash(raw), v = W.out  -> v_sm.
// Mainloop: per (b,l): logits[n] = u[l,:].v[n,:]; c = softmax_n; s[n,:] += c*u.
// Writes this block's partial s into g_s_part[iter-1].
// grid (K3_CHUNKS, BB), 128 threads (4 warps, 64 l's each).
// ---------------------------------------------------------------------------
__global__ void __launch_bounds__(128, 2) k3_route(const float* __restrict__ u,
                                                   const float* __restrict__ W,
                                                   int iter) {
    const int b = blockIdx.y, chunk = blockIdx.x;
    const int t = threadIdx.x;
    const int w = t >> 5;
    const int lane = t & 31;            // lane == capsule index n in mainloop

    // SB serves two roles (disjoint in time):
    //   prologue: [0..2047] s_sm, [2048..2559] raw
    //   mainloop: s_blk[w][n][65] = SB[w*2080 + n*65 + i]
    __shared__ float SB[K3_WARPS * NC * 65];   // 8320 floats
    __shared__ float v_sm[NC * 65];            // padded, conflict-free
    __shared__ float u_buf[K3_WARPS][2][64];
    __shared__ float norm_sm[NC];

    // ---- prologue ----
    if (iter == 1) {
        if (t < DIN) {
            float a = 0.f;
            #pragma unroll
            for (int c = 0; c < K1_CHUNKS; c++) a += g_colsum_part[b][c][t];
            SB[t] = a * (1.0f / 32.0f);        // cs[i], same for all n
        }
        __syncthreads();
        for (int o = t; o < OUTD; o += 128) {  // coalesced W columns
            float r = 0.f;
            #pragma unroll
            for (int i = 0; i < DIN; i++)
                r = fmaf(SB[i], W[(size_t)i * OUTD + o], r);
            SB[2048 + o] = r;
        }
    } else {
        const float* base = &g_s_part[0][b][0][0][0];
        for (int e = t; e < NC * DIN; e += 128) {
            float a = 0.f;
            #pragma unroll
            for (int c = 0; c < K3_CHUNKS; c++) a += base[(size_t)c * NC * DIN + e];
            SB[e] = a;                         // s_sm[n][i]
        }
        __syncthreads();
        for (int o = t; o < OUTD; o += 128) {
            const int n = o >> 4;
            float r = 0.f;
            #pragma unroll
            for (int i = 0; i < DIN; i++)
                r = fmaf(SB[n * DIN + i], W[(size_t)i * OUTD + o], r);
            SB[2048 + o] = r;
        }
    }
    __syncthreads();
    if (t < NC) {
        float s2 = 0.f;
        #pragma unroll
        for (int d = 0; d < DC; d++) {
            float r = SB[2048 + t * DC + d];
            s2 = fmaf(r, r, s2);
        }
        norm_sm[t] = rsqrtf(s2 + EPSQ);
    }
    __syncthreads();
    for (int e = t; e < NC * DIN; e += 128) {
        const int n = e >> 6, i = e & 63;
        const float4* Wr = (const float4*)(W + (size_t)i * OUTD + n * DC);
        const float4* Rr = (const float4*)(SB + 2048 + n * DC);
        float r = 0.f;
        #pragma unroll
        for (int q = 0; q < 4; q++) {
            float4 wv = Wr[q], rv = Rr[q];
            r = fmaf(wv.x, rv.x, r); r = fmaf(wv.y, rv.y, r);
            r = fmaf(wv.z, rv.z, r); r = fmaf(wv.w, rv.w, r);
        }
        v_sm[n * 65 + i] = r * norm_sm[n];     // v[n][i]
    }
    __syncthreads();

    // ---- mainloop (proven scalar form) ----
    float4 v4[16];
    #pragma unroll
    for (int k = 0; k < 16; k++) {             // scalar LDS, conflict-free (stride 65)
        v4[k].x = v_sm[lane * 65 + 4 * k + 0];
        v4[k].y = v_sm[lane * 65 + 4 * k + 1];
        v4[k].z = v_sm[lane * 65 + 4 * k + 2];
        v4[k].w = v_sm[lane * 65 + 4 * k + 3];
    }

    float4 s4[16];
    #pragma unroll
    for (int k = 0; k < 16; k++) s4[k] = make_float4(0.f, 0.f, 0.f, 0.f);

    const int l0 = chunk * (K3_WARPS * K3_LPW) + w * K3_LPW;
    const float* ub = u + ((size_t)b * LL + l0) * DIN;

    for (int j = 0; j < K3_LPW; j += 2) {
        float2 ra = ((const float2*)(ub + (size_t)j * DIN))[lane];
        float2 rb = ((const float2*)(ub + (size_t)(j + 1) * DIN))[lane];
        __syncwarp();
        ((float2*)u_buf[w][0])[lane] = ra;
        ((float2*)u_buf[w][1])[lane] = rb;
        __syncwarp();
        const float4* uA = (const float4*)u_buf[w][0];
        const float4* uB = (const float4*)u_buf[w][1];

        float lA0 = 0.f, lA1 = 0.f, lB0 = 0.f, lB1 = 0.f;
        #pragma unroll
        for (int k = 0; k < 16; k += 2) {
            float4 xA = uA[k], yA = uA[k + 1];
            float4 xB = uB[k], yB = uB[k + 1];
            lA0 = fmaf(xA.x, v4[k].x, lA0);     lA0 = fmaf(xA.y, v4[k].y, lA0);
            lA0 = fmaf(xA.z, v4[k].z, lA0);     lA0 = fmaf(xA.w, v4[k].w, lA0);
            lA1 = fmaf(yA.x, v4[k + 1].x, lA1); lA1 = fmaf(yA.y, v4[k + 1].y, lA1);
            lA1 = fmaf(yA.z, v4[k + 1].z, lA1); lA1 = fmaf(yA.w, v4[k + 1].w, lA1);
            lB0 = fmaf(xB.x, v4[k].x, lB0);     lB0 = fmaf(xB.y, v4[k].y, lB0);
            lB0 = fmaf(xB.z, v4[k].z, lB0);     lB0 = fmaf(xB.w, v4[k].w, lB0);
            lB1 = fmaf(yB.x, v4[k + 1].x, lB1); lB1 = fmaf(yB.y, v4[k + 1].y, lB1);
            lB1 = fmaf(yB.z, v4[k + 1].z, lB1); lB1 = fmaf(yB.w, v4[k + 1].w, lB1);
        }
        float eA = __expf(lA0 + lA1);
        float eB = __expf(lB0 + lB1);
        float sA = eA, sB = eB;
        #pragma unroll
        for (int off = 16; off; off >>= 1) {
            sA += __shfl_xor_sync(0xffffffffu, sA, off);
            sB += __shfl_xor_sync(0xffffffffu, sB, off);
        }
        float cA = __fdividef(eA, sA);
        float cB = __fdividef(eB, sB);

        #pragma unroll
        for (int k = 0; k < 16; k++) {
            float4 xA = uA[k], xB = uB[k];
            s4[k].x = fmaf(cA, xA.x, fmaf(cB, xB.x, s4[k].x));
            s4[k].y = fmaf(cA, xA.y, fmaf(cB, xB.y, s4[k].y));
            s4[k].z = fmaf(cA, xA.z, fmaf(cB, xB.z, s4[k].z));
            s4[k].w = fmaf(cA, xA.w, fmaf(cB, xB.w, s4[k].w));
        }
    }

    // dump register s into SB (s_blk role; prologue data dead by now)
    __syncthreads();          // ensure all prologue reads of SB are done block-wide
    #pragma unroll
    for (int k = 0; k < 16; k++) {
        SB[w * 2080 + lane * 65 + 4 * k + 0] = s4[k].x;
        SB[w * 2080 + lane * 65 + 4 * k + 1] = s4[k].y;
        SB[w * 2080 + lane * 65 + 4 * k + 2] = s4[k].z;
        SB[w * 2080 + lane * 65 + 4 * k + 3] = s4[k].w;
    }
    __syncthreads();

    float* outp = &g_s_part[iter - 1][b][chunk][0][0];
    for (int e = t; e < NC * DIN; e += 128) {
        int n = e >> 6, i = e & 63;
        outp[e] = SB[0 * 2080 + n * 65 + i] + SB[1 * 2080 + n * 65 + i]
                + SB[2 * 2080 + n * 65 + i] + SB[3 * 2080 + n * 65 + i];
    }
}

// ---------------------------------------------------------------------------
// K2f: final epilogue only. grid (NC, BB), 64 threads.
// Reduce g_s_part[1], raw = s.W, squash, write d_out.
// ---------------------------------------------------------------------------
__global__ void __launch_bounds__(64, 16) k2_final(const float* __restrict__ W,
                                                   float* __restrict__ out_final) {
    const int n = blockIdx.x, b = blockIdx.y;
    const int t = threadIdx.x;        // 0..63 == element index i

    __shared__ float s_sm[DIN];

    float a = 0.f;
    #pragma unroll
    for (int c = 0; c < K3_CHUNKS; c++)
        a += g_s_part[1][b][c][n][t];
    s_sm[t] = a;
    __syncthreads();

    if (t < 32) {
        float raw = 0.f;
        if (t < DC) {
            const float* Wc = W + (size_t)n * DC + t;
            #pragma unroll
            for (int i = 0; i < DIN; i++)
                raw = fmaf(s_sm[i], Wc[(size_t)i * OUTD], raw);
        }
        float s2 = raw * raw;
        #pragma unroll
        for (int off = 8; off; off >>= 1)
            s2 += __shfl_xor_sync(0xffffffffu, s2, off, 16);
        float o = raw * rsqrtf(s2 + EPSQ);
        if (t < DC)
            out_final[(size_t)b * OUTD + (size_t)n * DC + t] = o;
    }
}

// ---------------------------------------------------------------------------
extern "C" void kernel_launch(void* const* d_in, const int* in_sizes, int n_in,
                              void* d_out, int out_size) {
    const float* u = (const float*)d_in[0];   // [32, 2048, 64]
    const float* W = (const float*)d_in[1];   // [1, 64, 512]
    float* out = (float*)d_out;               // [32, 32, 16]

    k1_colsum<<<dim3(K1_CHUNKS, BB), 256>>>(u);
    k3_route<<<dim3(K3_CHUNKS, BB), 128>>>(u, W, 1);  // prologue(iter0) + routing 1
    k3_route<<<dim3(K3_CHUNKS, BB), 128>>>(u, W, 2);  // prologue(iter1) + routing 2
    k2_final<<<dim3(NC, BB), 64>>>(W, out);           // final squash -> d_out
}